// round 2
// baseline (speedup 1.0000x reference)
#include <cuda_runtime.h>

#define N_NODES 50000
#define E_EDGES 800000
#define IN_DIM  128
#define OUT_DIM 64

// ---------------- scratch (device globals; allocation-free) ----------------
__device__ __align__(16) float g_z[N_NODES * OUT_DIM];   // 12.8 MB (L2-resident)
__device__ float g_s1[N_NODES];
__device__ float g_s2[N_NODES];
__device__ float g_e[E_EDGES];          // leaky-relu attention logits (edge order)
__device__ int   g_deg[N_NODES];
__device__ int   g_off[N_NODES + 1];    // CSR offsets by dst
__device__ int   g_cur[N_NODES];        // running fill cursor
__device__ int   g_csrc[E_EDGES];       // CSR: src node per slot
__device__ float g_ce[E_EDGES];         // CSR: logit per slot

// ============================================================================
// K1: z = h @ W_fc^T ; s1 = z.w1 ; s2 = z.w2 ; zero deg
// One warp computes 4 full node rows (register tiling 2 outputs x 4 nodes).
// ============================================================================
__global__ void __launch_bounds__(128) k1_node(
    const float* __restrict__ h,
    const float* __restrict__ W,     // [64][128] row-major
    const float* __restrict__ attn)  // [192] = w1 | w2 | w3
{
    __shared__ __align__(16) float Wts[IN_DIM * 66];      // transposed, padded
    __shared__ __align__(16) float hw[4][IN_DIM][4];      // [warp][k][node-slot]

    const int tid = threadIdx.x;

    for (int i = tid; i < OUT_DIM * IN_DIM; i += blockDim.x) {
        int j = i >> 7;
        int k = i & 127;
        Wts[k * 66 + j] = W[i];
    }
    __syncthreads();

    const int w = tid >> 5;
    const int l = tid & 31;

    const float2 w1 = ((const float2*)attn)[l];
    const float2 w2 = ((const float2*)(attn + OUT_DIM))[l];

    const int ntasks_stride = gridDim.x * 4;
    for (int task = blockIdx.x * 4 + w; task < N_NODES / 4; task += ntasks_stride) {
        const int node0 = task * 4;

        #pragma unroll
        for (int m = 0; m < 4; m++) {
            const float* hp = h + (size_t)(node0 + m) * IN_DIM;
            #pragma unroll
            for (int t = 0; t < 4; t++)
                hw[w][t * 32 + l][m] = hp[t * 32 + l];
        }
        __syncwarp();

        float a0x = 0.f, a0y = 0.f, a0z = 0.f, a0w = 0.f;
        float a1x = 0.f, a1y = 0.f, a1z = 0.f, a1w = 0.f;
        #pragma unroll 16
        for (int k = 0; k < IN_DIM; k++) {
            const float4 hq = *(const float4*)&hw[w][k][0];
            const float2 wv = *(const float2*)&Wts[k * 66 + 2 * l];
            a0x += wv.x * hq.x; a0y += wv.x * hq.y; a0z += wv.x * hq.z; a0w += wv.x * hq.w;
            a1x += wv.y * hq.x; a1y += wv.y * hq.y; a1z += wv.y * hq.z; a1w += wv.y * hq.w;
        }
        __syncwarp();

        const float acc0[4] = {a0x, a0y, a0z, a0w};
        const float acc1[4] = {a1x, a1y, a1z, a1w};
        #pragma unroll
        for (int m = 0; m < 4; m++) {
            const int node = node0 + m;
            const float zx = acc0[m], zy = acc1[m];
            *(float2*)&g_z[(size_t)node * OUT_DIM + 2 * l] = make_float2(zx, zy);
            float v1 = zx * w1.x + zy * w1.y;
            float v2 = zx * w2.x + zy * w2.y;
            #pragma unroll
            for (int off = 16; off; off >>= 1) {
                v1 += __shfl_xor_sync(0xffffffffu, v1, off);
                v2 += __shfl_xor_sync(0xffffffffu, v2, off);
            }
            if (l == 0) {
                g_s1[node] = v1;
                g_s2[node] = v2;
                g_deg[node] = 0;
            }
        }
    }
}

// ============================================================================
// K2: per-edge logits + deg count. Half-warp (16 lanes) per edge.
// ============================================================================
__global__ void __launch_bounds__(256) k2_edge(
    const float* __restrict__ rh,
    const float* __restrict__ attn,
    const int* __restrict__ src,
    const int* __restrict__ dst)
{
    const int tid = blockIdx.x * blockDim.x + threadIdx.x;
    const int hw_id = tid >> 4;
    const int l = tid & 15;
    const int nhw = (gridDim.x * blockDim.x) >> 4;

    const float4 w3 = ((const float4*)(attn + 2 * OUT_DIM))[l];

    for (int e = hw_id; e < E_EDGES; e += nhw) {
        const float4 r = ((const float4*)(rh + (size_t)e * OUT_DIM))[l];
        float p = r.x * w3.x + r.y * w3.y + r.z * w3.z + r.w * w3.w;
        p += __shfl_xor_sync(0xffffffffu, p, 8);
        p += __shfl_xor_sync(0xffffffffu, p, 4);
        p += __shfl_xor_sync(0xffffffffu, p, 2);
        p += __shfl_xor_sync(0xffffffffu, p, 1);
        if (l == 0) {
            const int s = src[e];
            const int d = dst[e];
            const float a = g_s1[s] + g_s2[d] + p;
            g_e[e] = (a > 0.f) ? a : 0.01f * a;   // leaky relu
            atomicAdd(&g_deg[d], 1);
        }
    }
}

// ============================================================================
// K3: single-block exclusive scan of deg -> off, cur
// ============================================================================
__global__ void __launch_bounds__(1024) k_scan()
{
    __shared__ int sums[1024];
    const int t = threadIdx.x;
    const int CH = (N_NODES + 1023) / 1024;   // 49
    const int beg = t * CH;
    const int end = min(beg + CH, N_NODES);

    int s = 0;
    for (int i = beg; i < end; i++) s += g_deg[i];
    sums[t] = s;
    __syncthreads();

    // Hillis-Steele inclusive scan
    for (int off = 1; off < 1024; off <<= 1) {
        int v = (t >= off) ? sums[t - off] : 0;
        __syncthreads();
        sums[t] += v;
        __syncthreads();
    }

    int run = (t > 0) ? sums[t - 1] : 0;
    for (int i = beg; i < end; i++) {
        g_off[i] = run;
        g_cur[i] = run;
        run += g_deg[i];
    }
    if (t == 0) g_off[N_NODES] = sums[1023];
}

// ============================================================================
// K4: fill CSR slots (scatter edge src + logit into dst-grouped arrays)
// ============================================================================
__global__ void __launch_bounds__(256) k_fill(
    const int* __restrict__ src,
    const int* __restrict__ dst)
{
    const int e = blockIdx.x * blockDim.x + threadIdx.x;
    if (e >= E_EDGES) return;
    const int d = dst[e];
    const int pos = atomicAdd(&g_cur[d], 1);
    g_csrc[pos] = src[e];
    g_ce[pos]   = g_e[e];
}

// ============================================================================
// K5: per-node (warp each): softmax over incoming edges + z gather-accumulate
//     fused with self-loop GEMV and relu epilogue. No atomics anywhere.
// ============================================================================
__global__ void __launch_bounds__(256) k_agg(
    const float* __restrict__ LW,   // [64][64] row-major = [k][j]
    float* __restrict__ out)
{
    __shared__ __align__(16) float Ls[OUT_DIM * OUT_DIM];
    for (int i = threadIdx.x; i < OUT_DIM * OUT_DIM; i += blockDim.x) Ls[i] = LW[i];
    __syncthreads();

    const int node = (blockIdx.x * blockDim.x + threadIdx.x) >> 5;
    const int l = threadIdx.x & 31;
    if (node >= N_NODES) return;

    const int beg = g_off[node];
    const int end = g_off[node + 1];

    if (beg == end) {    // deg == 0 -> output row is zero
        *(float2*)&out[(size_t)node * OUT_DIM + 2 * l] = make_float2(0.f, 0.f);
        return;
    }

    // ---- self-loop: z[node] @ LW, lane l owns output dims {2l, 2l+1} ----
    const float2 zn = *(const float2*)&g_z[(size_t)node * OUT_DIM + 2 * l];
    float slx = 0.f, sly = 0.f;
    #pragma unroll
    for (int k = 0; k < OUT_DIM; k++) {
        const float zk = __shfl_sync(0xffffffffu, (k & 1) ? zn.y : zn.x, k >> 1);
        const float2 lv = *(const float2*)&Ls[k * OUT_DIM + 2 * l];
        slx += zk * lv.x;
        sly += zk * lv.y;
    }

    // ---- segment max (register reduce) ----
    float mloc = -3.4e38f;
    for (int i = beg + l; i < end; i += 32) mloc = fmaxf(mloc, g_ce[i]);
    #pragma unroll
    for (int off = 16; off; off >>= 1)
        mloc = fmaxf(mloc, __shfl_xor_sync(0xffffffffu, mloc, off));

    // ---- exp + gather-accumulate (prefetch depth 4) ----
    float accx = 0.f, accy = 0.f, denom = 0.f;
    for (int base = beg; base < end; base += 32) {
        const int idx = base + l;
        const bool valid = idx < end;
        const float ex_l = valid ? __expf(g_ce[idx] - mloc) : 0.f;
        const int   sv   = valid ? g_csrc[idx] : 0;
        const int cnt = min(32, end - base);

        int j = 0;
        for (; j + 4 <= cnt; j += 4) {
            const int s0 = __shfl_sync(0xffffffffu, sv, j);
            const int s1 = __shfl_sync(0xffffffffu, sv, j + 1);
            const int s2 = __shfl_sync(0xffffffffu, sv, j + 2);
            const int s3 = __shfl_sync(0xffffffffu, sv, j + 3);
            const float e0 = __shfl_sync(0xffffffffu, ex_l, j);
            const float e1 = __shfl_sync(0xffffffffu, ex_l, j + 1);
            const float e2 = __shfl_sync(0xffffffffu, ex_l, j + 2);
            const float e3 = __shfl_sync(0xffffffffu, ex_l, j + 3);
            const float2 z0 = *(const float2*)&g_z[(size_t)s0 * OUT_DIM + 2 * l];
            const float2 z1 = *(const float2*)&g_z[(size_t)s1 * OUT_DIM + 2 * l];
            const float2 z2 = *(const float2*)&g_z[(size_t)s2 * OUT_DIM + 2 * l];
            const float2 z3 = *(const float2*)&g_z[(size_t)s3 * OUT_DIM + 2 * l];
            denom += (e0 + e1) + (e2 + e3);
            accx += e0 * z0.x; accy += e0 * z0.y;
            accx += e1 * z1.x; accy += e1 * z1.y;
            accx += e2 * z2.x; accy += e2 * z2.y;
            accx += e3 * z3.x; accy += e3 * z3.y;
        }
        for (; j < cnt; j++) {
            const int   s  = __shfl_sync(0xffffffffu, sv, j);
            const float ex = __shfl_sync(0xffffffffu, ex_l, j);
            const float2 zz = *(const float2*)&g_z[(size_t)s * OUT_DIM + 2 * l];
            denom += ex;
            accx += ex * zz.x;
            accy += ex * zz.y;
        }
    }

    const float inv = 1.0f / denom;
    float2 o;
    o.x = fmaxf(accx * inv + slx, 0.f);
    o.y = fmaxf(accy * inv + sly, 0.f);
    *(float2*)&out[(size_t)node * OUT_DIM + 2 * l] = o;
}

// ============================================================================
// launch
// ============================================================================
extern "C" void kernel_launch(void* const* d_in, const int* in_sizes, int n_in,
                              void* d_out, int out_size)
{
    const float* h    = (const float*)d_in[0];
    const float* rh   = (const float*)d_in[1];
    const float* W    = (const float*)d_in[2];
    const float* attn = (const float*)d_in[3];
    const float* LW   = (const float*)d_in[4];
    const int*   src  = (const int*)d_in[5];
    const int*   dst  = (const int*)d_in[6];
    float* out = (float*)d_out;

    k1_node<<<1024, 128>>>(h, W, attn);
    k2_edge<<<1184, 256>>>(rh, attn, src, dst);
    k_scan<<<1, 1024>>>();
    k_fill<<<(E_EDGES + 255) / 256, 256>>>(src, dst);
    k_agg<<<(N_NODES * 32 + 255) / 256, 256>>>(LW, out);
}

// round 3
// speedup vs baseline: 1.0118x; 1.0118x over previous
#include <cuda_runtime.h>

#define N_NODES 50000
#define E_EDGES 800000
#define IN_DIM  128
#define OUT_DIM 64

// ---------------- scratch (device globals; allocation-free) ----------------
__device__ __align__(16) float g_z[N_NODES * OUT_DIM];   // 12.8 MB (L2-resident)
__device__ float g_s1[N_NODES];
__device__ float g_s2[N_NODES];
__device__ int   g_deg[N_NODES];
__device__ int   g_off[N_NODES + 1];    // CSR offsets by dst
__device__ int   g_cur[N_NODES];        // running fill cursor
__device__ __align__(8) int2 g_cedge[E_EDGES];  // packed {src, logit_bits} per CSR slot

// ============================================================================
// K1: z = h @ W_fc^T ; s1 = z.w1 ; s2 = z.w2 ; zero deg
// One warp computes 4 full node rows (register tiling 2 outputs x 4 nodes).
// ============================================================================
__global__ void __launch_bounds__(128) k1_node(
    const float* __restrict__ h,
    const float* __restrict__ W,     // [64][128] row-major
    const float* __restrict__ attn)  // [192] = w1 | w2 | w3
{
    __shared__ __align__(16) float Wts[IN_DIM * 66];      // transposed, padded
    __shared__ __align__(16) float hw[4][IN_DIM][4];      // [warp][k][node-slot]

    const int tid = threadIdx.x;

    for (int i = tid; i < OUT_DIM * IN_DIM; i += blockDim.x) {
        int j = i >> 7;
        int k = i & 127;
        Wts[k * 66 + j] = W[i];
    }
    __syncthreads();

    const int w = tid >> 5;
    const int l = tid & 31;

    const float2 w1 = ((const float2*)attn)[l];
    const float2 w2 = ((const float2*)(attn + OUT_DIM))[l];

    const int ntasks_stride = gridDim.x * 4;
    for (int task = blockIdx.x * 4 + w; task < N_NODES / 4; task += ntasks_stride) {
        const int node0 = task * 4;

        #pragma unroll
        for (int m = 0; m < 4; m++) {
            const float* hp = h + (size_t)(node0 + m) * IN_DIM;
            #pragma unroll
            for (int t = 0; t < 4; t++)
                hw[w][t * 32 + l][m] = hp[t * 32 + l];
        }
        __syncwarp();

        float a0x = 0.f, a0y = 0.f, a0z = 0.f, a0w = 0.f;
        float a1x = 0.f, a1y = 0.f, a1z = 0.f, a1w = 0.f;
        #pragma unroll 16
        for (int k = 0; k < IN_DIM; k++) {
            const float4 hq = *(const float4*)&hw[w][k][0];
            const float2 wv = *(const float2*)&Wts[k * 66 + 2 * l];
            a0x += wv.x * hq.x; a0y += wv.x * hq.y; a0z += wv.x * hq.z; a0w += wv.x * hq.w;
            a1x += wv.y * hq.x; a1y += wv.y * hq.y; a1z += wv.y * hq.z; a1w += wv.y * hq.w;
        }
        __syncwarp();

        const float acc0[4] = {a0x, a0y, a0z, a0w};
        const float acc1[4] = {a1x, a1y, a1z, a1w};
        #pragma unroll
        for (int m = 0; m < 4; m++) {
            const int node = node0 + m;
            const float zx = acc0[m], zy = acc1[m];
            *(float2*)&g_z[(size_t)node * OUT_DIM + 2 * l] = make_float2(zx, zy);
            float v1 = zx * w1.x + zy * w1.y;
            float v2 = zx * w2.x + zy * w2.y;
            #pragma unroll
            for (int off = 16; off; off >>= 1) {
                v1 += __shfl_xor_sync(0xffffffffu, v1, off);
                v2 += __shfl_xor_sync(0xffffffffu, v2, off);
            }
            if (l == 0) {
                g_s1[node] = v1;
                g_s2[node] = v2;
                g_deg[node] = 0;
            }
        }
    }
}

// ============================================================================
// K_count: degree histogram over dst
// ============================================================================
__global__ void __launch_bounds__(256) k_count(const int* __restrict__ dst)
{
    const int e = blockIdx.x * blockDim.x + threadIdx.x;
    if (e < E_EDGES) atomicAdd(&g_deg[dst[e]], 1);
}

// ============================================================================
// K_scan: single-block exclusive scan of deg -> off, cur
// ============================================================================
__global__ void __launch_bounds__(1024) k_scan()
{
    __shared__ int sums[1024];
    const int t = threadIdx.x;
    const int CH = (N_NODES + 1023) / 1024;   // 49
    const int beg = t * CH;
    const int end = min(beg + CH, N_NODES);

    int s = 0;
    for (int i = beg; i < end; i++) s += g_deg[i];
    sums[t] = s;
    __syncthreads();

    for (int off = 1; off < 1024; off <<= 1) {
        int v = (t >= off) ? sums[t - off] : 0;
        __syncthreads();
        sums[t] += v;
        __syncthreads();
    }

    int run = (t > 0) ? sums[t - 1] : 0;
    for (int i = beg; i < end; i++) {
        g_off[i] = run;
        g_cur[i] = run;
        run += g_deg[i];
    }
    if (t == 0) g_off[N_NODES] = sums[1023];
}

// ============================================================================
// K2: per-edge logits + direct CSR scatter. Half-warp (16 lanes) per edge.
// Scatter of a single packed int2 rides under the HBM-bound r_h stream.
// ============================================================================
__global__ void __launch_bounds__(256) k2_scatter(
    const float* __restrict__ rh,
    const float* __restrict__ attn,
    const int* __restrict__ src,
    const int* __restrict__ dst)
{
    const int tid = blockIdx.x * blockDim.x + threadIdx.x;
    const int hw_id = tid >> 4;
    const int l = tid & 15;
    const int nhw = (gridDim.x * blockDim.x) >> 4;

    const float4 w3 = ((const float4*)(attn + 2 * OUT_DIM))[l];

    for (int e = hw_id; e < E_EDGES; e += nhw) {
        const float4 r = ((const float4*)(rh + (size_t)e * OUT_DIM))[l];
        float p = r.x * w3.x + r.y * w3.y + r.z * w3.z + r.w * w3.w;
        p += __shfl_xor_sync(0xffffffffu, p, 8);
        p += __shfl_xor_sync(0xffffffffu, p, 4);
        p += __shfl_xor_sync(0xffffffffu, p, 2);
        p += __shfl_xor_sync(0xffffffffu, p, 1);
        if (l == 0) {
            const int s = src[e];
            const int d = dst[e];
            const float a = g_s1[s] + g_s2[d] + p;
            const float ev = (a > 0.f) ? a : 0.01f * a;   // leaky relu
            const int pos = atomicAdd(&g_cur[d], 1);
            g_cedge[pos] = make_int2(s, __float_as_int(ev));
        }
    }
}

// ============================================================================
// K_agg: half-warp (16 lanes) per node, lane owns 4 output dims (float4).
// softmax over incoming edges + z gather-accumulate + self-loop GEMV + relu.
// No shfl-broadcast of payload data, no atomics.
// ============================================================================
__global__ void __launch_bounds__(256) k_agg(
    const float* __restrict__ LW,   // [64][64] row-major = [k][j]
    float* __restrict__ out)
{
    __shared__ __align__(16) float Ls[OUT_DIM * OUT_DIM];
    for (int i = threadIdx.x; i < OUT_DIM * OUT_DIM / 4; i += blockDim.x)
        ((float4*)Ls)[i] = ((const float4*)LW)[i];
    __syncthreads();

    const int node = (blockIdx.x * blockDim.x + threadIdx.x) >> 4;
    const int l = threadIdx.x & 15;
    if (node >= N_NODES) return;

    const int beg = g_off[node];
    const int end = g_off[node + 1];

    float4 o = make_float4(0.f, 0.f, 0.f, 0.f);
    if (beg < end) {
        // ---- segment max (strided per-lane, width-16 reduce) ----
        float m = -3.4e38f;
        for (int i = beg + l; i < end; i += 16)
            m = fmaxf(m, __int_as_float(g_cedge[i].y));
        #pragma unroll
        for (int off = 8; off; off >>= 1)
            m = fmaxf(m, __shfl_xor_sync(0xffffffffu, m, off, 16));

        // ---- exp + gather-accumulate (unroll x2 for MLP) ----
        float4 acc = make_float4(0.f, 0.f, 0.f, 0.f);
        float denom = 0.f;
        int i = beg;
        for (; i + 2 <= end; i += 2) {
            const int2 e0 = g_cedge[i];
            const int2 e1 = g_cedge[i + 1];
            const float x0 = __expf(__int_as_float(e0.y) - m);
            const float x1 = __expf(__int_as_float(e1.y) - m);
            const float4 z0 = *(const float4*)&g_z[(size_t)e0.x * OUT_DIM + 4 * l];
            const float4 z1 = *(const float4*)&g_z[(size_t)e1.x * OUT_DIM + 4 * l];
            denom += x0 + x1;
            acc.x += x0 * z0.x + x1 * z1.x;
            acc.y += x0 * z0.y + x1 * z1.y;
            acc.z += x0 * z0.z + x1 * z1.z;
            acc.w += x0 * z0.w + x1 * z1.w;
        }
        if (i < end) {
            const int2 e0 = g_cedge[i];
            const float x0 = __expf(__int_as_float(e0.y) - m);
            const float4 z0 = *(const float4*)&g_z[(size_t)e0.x * OUT_DIM + 4 * l];
            denom += x0;
            acc.x += x0 * z0.x;
            acc.y += x0 * z0.y;
            acc.z += x0 * z0.z;
            acc.w += x0 * z0.w;
        }

        // ---- self-loop: z[node] @ LW via width-16 shfl broadcast ----
        const float4 zq = *(const float4*)&g_z[(size_t)node * OUT_DIM + 4 * l];
        const float zv[4] = {zq.x, zq.y, zq.z, zq.w};
        float4 sl = make_float4(0.f, 0.f, 0.f, 0.f);
        #pragma unroll
        for (int k = 0; k < OUT_DIM; k++) {
            const float zk = __shfl_sync(0xffffffffu, zv[k & 3], k >> 2, 16);
            const float4 lw = *(const float4*)&Ls[k * OUT_DIM + 4 * l];
            sl.x += zk * lw.x;
            sl.y += zk * lw.y;
            sl.z += zk * lw.z;
            sl.w += zk * lw.w;
        }

        const float inv = 1.0f / denom;
        o.x = fmaxf(acc.x * inv + sl.x, 0.f);
        o.y = fmaxf(acc.y * inv + sl.y, 0.f);
        o.z = fmaxf(acc.z * inv + sl.z, 0.f);
        o.w = fmaxf(acc.w * inv + sl.w, 0.f);
    }
    *(float4*)&out[(size_t)node * OUT_DIM + 4 * l] = o;
}

// ============================================================================
// launch
// ============================================================================
extern "C" void kernel_launch(void* const* d_in, const int* in_sizes, int n_in,
                              void* d_out, int out_size)
{
    const float* h    = (const float*)d_in[0];
    const float* rh   = (const float*)d_in[1];
    const float* W    = (const float*)d_in[2];
    const float* attn = (const float*)d_in[3];
    const float* LW   = (const float*)d_in[4];
    const int*   src  = (const int*)d_in[5];
    const int*   dst  = (const int*)d_in[6];
    float* out = (float*)d_out;

    k1_node<<<1024, 128>>>(h, W, attn);
    k_count<<<(E_EDGES + 255) / 256, 256>>>(dst);
    k_scan<<<1, 1024>>>();
    k2_scatter<<<1184, 256>>>(rh, attn, src, dst);
    k_agg<<<(N_NODES * 16 + 255) / 256, 256>>>(LW, out);
}

// round 4
// speedup vs baseline: 1.1543x; 1.1409x over previous
#include <cuda_runtime.h>

#define N_NODES 50000
#define E_EDGES 800000
#define IN_DIM  128
#define OUT_DIM 64

// ---------------- scratch (device globals; allocation-free) ----------------
__device__ __align__(16) float g_z[N_NODES * OUT_DIM];   // 12.8 MB (L2-resident)
__device__ float g_s1[N_NODES];
__device__ float g_s2[N_NODES];
__device__ int   g_deg[N_NODES];
__device__ int   g_off[N_NODES + 1];    // CSR offsets by dst
__device__ int   g_cur[N_NODES];        // running fill cursor
__device__ __align__(8) int2 g_cedge[E_EDGES];  // packed {src, exp_bits} per CSR slot

// ============================================================================
// K1: z = h @ W_fc^T ; s1 = z.w1 ; s2 = z.w2 ; zero deg
// ============================================================================
__global__ void __launch_bounds__(128) k1_node(
    const float* __restrict__ h,
    const float* __restrict__ W,     // [64][128] row-major
    const float* __restrict__ attn)  // [192] = w1 | w2 | w3
{
    __shared__ __align__(16) float Wts[IN_DIM * 66];      // transposed, padded
    __shared__ __align__(16) float hw[4][IN_DIM][4];      // [warp][k][node-slot]

    const int tid = threadIdx.x;

    for (int i = tid; i < OUT_DIM * IN_DIM; i += blockDim.x) {
        int j = i >> 7;
        int k = i & 127;
        Wts[k * 66 + j] = W[i];
    }
    __syncthreads();

    const int w = tid >> 5;
    const int l = tid & 31;

    const float2 w1 = ((const float2*)attn)[l];
    const float2 w2 = ((const float2*)(attn + OUT_DIM))[l];

    const int ntasks_stride = gridDim.x * 4;
    for (int task = blockIdx.x * 4 + w; task < N_NODES / 4; task += ntasks_stride) {
        const int node0 = task * 4;

        #pragma unroll
        for (int m = 0; m < 4; m++) {
            const float* hp = h + (size_t)(node0 + m) * IN_DIM;
            #pragma unroll
            for (int t = 0; t < 4; t++)
                hw[w][t * 32 + l][m] = hp[t * 32 + l];
        }
        __syncwarp();

        float a0x = 0.f, a0y = 0.f, a0z = 0.f, a0w = 0.f;
        float a1x = 0.f, a1y = 0.f, a1z = 0.f, a1w = 0.f;
        #pragma unroll 16
        for (int k = 0; k < IN_DIM; k++) {
            const float4 hq = *(const float4*)&hw[w][k][0];
            const float2 wv = *(const float2*)&Wts[k * 66 + 2 * l];
            a0x += wv.x * hq.x; a0y += wv.x * hq.y; a0z += wv.x * hq.z; a0w += wv.x * hq.w;
            a1x += wv.y * hq.x; a1y += wv.y * hq.y; a1z += wv.y * hq.z; a1w += wv.y * hq.w;
        }
        __syncwarp();

        const float acc0[4] = {a0x, a0y, a0z, a0w};
        const float acc1[4] = {a1x, a1y, a1z, a1w};
        #pragma unroll
        for (int m = 0; m < 4; m++) {
            const int node = node0 + m;
            const float zx = acc0[m], zy = acc1[m];
            *(float2*)&g_z[(size_t)node * OUT_DIM + 2 * l] = make_float2(zx, zy);
            float v1 = zx * w1.x + zy * w1.y;
            float v2 = zx * w2.x + zy * w2.y;
            #pragma unroll
            for (int off = 16; off; off >>= 1) {
                v1 += __shfl_xor_sync(0xffffffffu, v1, off);
                v2 += __shfl_xor_sync(0xffffffffu, v2, off);
            }
            if (l == 0) {
                g_s1[node] = v1;
                g_s2[node] = v2;
                g_deg[node] = 0;
            }
        }
    }
}

// ============================================================================
// K_count: degree histogram over dst
// ============================================================================
__global__ void __launch_bounds__(256) k_count(const int* __restrict__ dst)
{
    const int e = blockIdx.x * blockDim.x + threadIdx.x;
    if (e < E_EDGES) atomicAdd(&g_deg[dst[e]], 1);
}

// ============================================================================
// K_scan: single-block exclusive scan of deg -> off, cur
// ============================================================================
__global__ void __launch_bounds__(1024) k_scan()
{
    __shared__ int sums[1024];
    const int t = threadIdx.x;
    const int CH = (N_NODES + 1023) / 1024;   // 49
    const int beg = t * CH;
    const int end = min(beg + CH, N_NODES);

    int s = 0;
    for (int i = beg; i < end; i++) s += g_deg[i];
    sums[t] = s;
    __syncthreads();

    for (int off = 1; off < 1024; off <<= 1) {
        int v = (t >= off) ? sums[t - off] : 0;
        __syncthreads();
        sums[t] += v;
        __syncthreads();
    }

    int run = (t > 0) ? sums[t - 1] : 0;
    for (int i = beg; i < end; i++) {
        g_off[i] = run;
        g_cur[i] = run;
        run += g_deg[i];
    }
    if (t == 0) g_off[N_NODES] = sums[1023];
}

// ============================================================================
// K2: logits -> exp -> direct CSR scatter. Half-warp per edge, 4 edges in
// flight per half-warp (MLP=4). Lanes 0-3 parallelize the scalar tail.
// E_EDGES % 4 == 0.
// ============================================================================
__global__ void __launch_bounds__(256) k2_scatter(
    const float* __restrict__ rh,
    const float* __restrict__ attn,
    const int* __restrict__ src,
    const int* __restrict__ dst)
{
    const int tid = blockIdx.x * blockDim.x + threadIdx.x;
    const int hw_id = tid >> 4;
    const int l = tid & 15;
    const int nhw = (gridDim.x * blockDim.x) >> 4;

    const float4 w3 = ((const float4*)(attn + 2 * OUT_DIM))[l];

    for (int e0 = hw_id * 4; e0 < E_EDGES; e0 += nhw * 4) {
        const float4 r0 = ((const float4*)(rh + (size_t)(e0 + 0) * OUT_DIM))[l];
        const float4 r1 = ((const float4*)(rh + (size_t)(e0 + 1) * OUT_DIM))[l];
        const float4 r2 = ((const float4*)(rh + (size_t)(e0 + 2) * OUT_DIM))[l];
        const float4 r3 = ((const float4*)(rh + (size_t)(e0 + 3) * OUT_DIM))[l];

        float p0 = r0.x * w3.x + r0.y * w3.y + r0.z * w3.z + r0.w * w3.w;
        float p1 = r1.x * w3.x + r1.y * w3.y + r1.z * w3.z + r1.w * w3.w;
        float p2 = r2.x * w3.x + r2.y * w3.y + r2.z * w3.z + r2.w * w3.w;
        float p3 = r3.x * w3.x + r3.y * w3.y + r3.z * w3.z + r3.w * w3.w;
        #pragma unroll
        for (int off = 8; off; off >>= 1) {
            p0 += __shfl_xor_sync(0xffffffffu, p0, off, 16);
            p1 += __shfl_xor_sync(0xffffffffu, p1, off, 16);
            p2 += __shfl_xor_sync(0xffffffffu, p2, off, 16);
            p3 += __shfl_xor_sync(0xffffffffu, p3, off, 16);
        }
        if (l < 4) {
            const int e = e0 + l;
            const float p = (l == 0) ? p0 : (l == 1) ? p1 : (l == 2) ? p2 : p3;
            const int s = src[e];
            const int d = dst[e];
            const float a = g_s1[s] + g_s2[d] + p;
            const float ev = (a > 0.f) ? a : 0.01f * a;   // leaky relu
            const float ex = __expf(ev);                  // no max-sub: |ev| small
            const int pos = atomicAdd(&g_cur[d], 1);
            g_cedge[pos] = make_int2(s, __float_as_int(ex));
        }
    }
}

// ============================================================================
// K_agg: full warp per node; half-warp per edge (2 edges/iter in flight per
// half-warp = 4 per warp). Payload already holds exp(e). No max pass.
// Fused self-loop GEMV (split across halves) + normalize + relu.
// ============================================================================
__global__ void __launch_bounds__(256) k_agg(
    const float* __restrict__ LW,   // [64][64] row-major = [k][j]
    float* __restrict__ out)
{
    __shared__ __align__(16) float Ls[OUT_DIM * OUT_DIM];
    for (int i = threadIdx.x; i < OUT_DIM * OUT_DIM / 4; i += blockDim.x)
        ((float4*)Ls)[i] = ((const float4*)LW)[i];
    __syncthreads();

    const int node = (blockIdx.x * blockDim.x + threadIdx.x) >> 5;
    const int l = threadIdx.x & 31;
    const int half = l >> 4;        // 0 or 1
    const int lh = l & 15;          // lane within half
    if (node >= N_NODES) return;

    const int beg = g_off[node];
    const int end = g_off[node + 1];

    if (beg == end) {
        if (half == 0)
            *(float4*)&out[(size_t)node * OUT_DIM + 4 * lh] = make_float4(0.f, 0.f, 0.f, 0.f);
        return;
    }

    // ---- gather-accumulate: this half handles edges beg+half, beg+half+2, ...
    float4 acc = make_float4(0.f, 0.f, 0.f, 0.f);
    float denom = 0.f;
    int i = beg + half;
    for (; i + 2 < end; i += 4) {
        const int2 e0 = g_cedge[i];
        const int2 e1 = g_cedge[i + 2];
        const float x0 = __int_as_float(e0.y);
        const float x1 = __int_as_float(e1.y);
        const float4 z0 = *(const float4*)&g_z[(size_t)e0.x * OUT_DIM + 4 * lh];
        const float4 z1 = *(const float4*)&g_z[(size_t)e1.x * OUT_DIM + 4 * lh];
        denom += x0 + x1;
        acc.x += x0 * z0.x + x1 * z1.x;
        acc.y += x0 * z0.y + x1 * z1.y;
        acc.z += x0 * z0.z + x1 * z1.z;
        acc.w += x0 * z0.w + x1 * z1.w;
    }
    for (; i < end; i += 2) {
        const int2 e0 = g_cedge[i];
        const float x0 = __int_as_float(e0.y);
        const float4 z0 = *(const float4*)&g_z[(size_t)e0.x * OUT_DIM + 4 * lh];
        denom += x0;
        acc.x += x0 * z0.x;
        acc.y += x0 * z0.y;
        acc.z += x0 * z0.z;
        acc.w += x0 * z0.w;
    }

    // ---- self-loop GEMV: half h covers k in [32h, 32h+32) ----
    const float2 zn = *(const float2*)&g_z[(size_t)node * OUT_DIM + 2 * l];
    float4 sl = make_float4(0.f, 0.f, 0.f, 0.f);
    #pragma unroll
    for (int kk = 0; kk < 32; kk++) {
        const int k = half * 32 + kk;
        const float zk = __shfl_sync(0xffffffffu, (k & 1) ? zn.y : zn.x, k >> 1);
        const float4 lw = *(const float4*)&Ls[k * OUT_DIM + 4 * lh];
        sl.x += zk * lw.x;
        sl.y += zk * lw.y;
        sl.z += zk * lw.z;
        sl.w += zk * lw.w;
    }

    // ---- combine halves (lane <-> lane+16) ----
    acc.x += __shfl_xor_sync(0xffffffffu, acc.x, 16);
    acc.y += __shfl_xor_sync(0xffffffffu, acc.y, 16);
    acc.z += __shfl_xor_sync(0xffffffffu, acc.z, 16);
    acc.w += __shfl_xor_sync(0xffffffffu, acc.w, 16);
    sl.x  += __shfl_xor_sync(0xffffffffu, sl.x, 16);
    sl.y  += __shfl_xor_sync(0xffffffffu, sl.y, 16);
    sl.z  += __shfl_xor_sync(0xffffffffu, sl.z, 16);
    sl.w  += __shfl_xor_sync(0xffffffffu, sl.w, 16);
    denom += __shfl_xor_sync(0xffffffffu, denom, 16);

    if (half == 0) {
        const float inv = 1.0f / denom;
        float4 o;
        o.x = fmaxf(acc.x * inv + sl.x, 0.f);
        o.y = fmaxf(acc.y * inv + sl.y, 0.f);
        o.z = fmaxf(acc.z * inv + sl.z, 0.f);
        o.w = fmaxf(acc.w * inv + sl.w, 0.f);
        *(float4*)&out[(size_t)node * OUT_DIM + 4 * lh] = o;
    }
}

// ============================================================================
// launch
// ============================================================================
extern "C" void kernel_launch(void* const* d_in, const int* in_sizes, int n_in,
                              void* d_out, int out_size)
{
    const float* h    = (const float*)d_in[0];
    const float* rh   = (const float*)d_in[1];
    const float* W    = (const float*)d_in[2];
    const float* attn = (const float*)d_in[3];
    const float* LW   = (const float*)d_in[4];
    const int*   src  = (const int*)d_in[5];
    const int*   dst  = (const int*)d_in[6];
    float* out = (float*)d_out;

    k1_node<<<1024, 128>>>(h, W, attn);
    k_count<<<(E_EDGES + 255) / 256, 256>>>(dst);
    k_scan<<<1, 1024>>>();
    k2_scatter<<<1184, 256>>>(rh, attn, src, dst);
    k_agg<<<(N_NODES * 32 + 255) / 256, 256>>>(LW, out);
}

// round 5
// speedup vs baseline: 1.7152x; 1.4859x over previous
#include <cuda_runtime.h>

#define N_NODES 50000
#define E_EDGES 800000
#define IN_DIM  128
#define OUT_DIM 64

#define SCAN_BLK 256
#define N_SBLK ((N_NODES + SCAN_BLK - 1) / SCAN_BLK)   // 196

// ---------------- scratch (device globals; allocation-free) ----------------
__device__ __align__(16) float g_z[N_NODES * OUT_DIM];   // 12.8 MB (L2-resident)
__device__ float g_s1[N_NODES];
__device__ float g_s2[N_NODES];
__device__ int   g_deg[N_NODES];
__device__ int   g_off[N_NODES + 1];    // CSR offsets by dst
__device__ int   g_cur[N_NODES];        // running fill cursor
__device__ int   g_bsum[N_SBLK];        // per-block degree sums
__device__ int   g_boff[N_SBLK];        // exclusive block offsets
__device__ __align__(8) int2 g_cedge[E_EDGES];  // packed {src, exp_bits} per CSR slot

// ============================================================================
// K1: z = h @ W_fc^T ; s1 = z.w1 ; s2 = z.w2 ; zero deg
// ============================================================================
__global__ void __launch_bounds__(128) k1_node(
    const float* __restrict__ h,
    const float* __restrict__ W,     // [64][128] row-major
    const float* __restrict__ attn)  // [192] = w1 | w2 | w3
{
    __shared__ __align__(16) float Wts[IN_DIM * 66];      // transposed, padded
    __shared__ __align__(16) float hw[4][IN_DIM][4];      // [warp][k][node-slot]

    const int tid = threadIdx.x;

    for (int i = tid; i < OUT_DIM * IN_DIM; i += blockDim.x) {
        int j = i >> 7;
        int k = i & 127;
        Wts[k * 66 + j] = W[i];
    }
    __syncthreads();

    const int w = tid >> 5;
    const int l = tid & 31;

    const float2 w1 = ((const float2*)attn)[l];
    const float2 w2 = ((const float2*)(attn + OUT_DIM))[l];

    const int ntasks_stride = gridDim.x * 4;
    for (int task = blockIdx.x * 4 + w; task < N_NODES / 4; task += ntasks_stride) {
        const int node0 = task * 4;

        #pragma unroll
        for (int m = 0; m < 4; m++) {
            const float* hp = h + (size_t)(node0 + m) * IN_DIM;
            #pragma unroll
            for (int t = 0; t < 4; t++)
                hw[w][t * 32 + l][m] = hp[t * 32 + l];
        }
        __syncwarp();

        float a0x = 0.f, a0y = 0.f, a0z = 0.f, a0w = 0.f;
        float a1x = 0.f, a1y = 0.f, a1z = 0.f, a1w = 0.f;
        #pragma unroll 16
        for (int k = 0; k < IN_DIM; k++) {
            const float4 hq = *(const float4*)&hw[w][k][0];
            const float2 wv = *(const float2*)&Wts[k * 66 + 2 * l];
            a0x += wv.x * hq.x; a0y += wv.x * hq.y; a0z += wv.x * hq.z; a0w += wv.x * hq.w;
            a1x += wv.y * hq.x; a1y += wv.y * hq.y; a1z += wv.y * hq.z; a1w += wv.y * hq.w;
        }
        __syncwarp();

        const float acc0[4] = {a0x, a0y, a0z, a0w};
        const float acc1[4] = {a1x, a1y, a1z, a1w};
        #pragma unroll
        for (int m = 0; m < 4; m++) {
            const int node = node0 + m;
            const float zx = acc0[m], zy = acc1[m];
            *(float2*)&g_z[(size_t)node * OUT_DIM + 2 * l] = make_float2(zx, zy);
            float v1 = zx * w1.x + zy * w1.y;
            float v2 = zx * w2.x + zy * w2.y;
            #pragma unroll
            for (int off = 16; off; off >>= 1) {
                v1 += __shfl_xor_sync(0xffffffffu, v1, off);
                v2 += __shfl_xor_sync(0xffffffffu, v2, off);
            }
            if (l == 0) {
                g_s1[node] = v1;
                g_s2[node] = v2;
                g_deg[node] = 0;
            }
        }
    }
}

// ============================================================================
// K_count: degree histogram over dst
// ============================================================================
__global__ void __launch_bounds__(256) k_count(const int* __restrict__ dst)
{
    const int e = blockIdx.x * blockDim.x + threadIdx.x;
    if (e < E_EDGES) atomicAdd(&g_deg[dst[e]], 1);
}

// ============================================================================
// Coalesced 3-phase scan of g_deg -> g_off / g_cur
// ============================================================================
__global__ void __launch_bounds__(SCAN_BLK) k_scanA()   // block sums
{
    __shared__ int red[SCAN_BLK / 32];
    const int gid = blockIdx.x * SCAN_BLK + threadIdx.x;
    int v = (gid < N_NODES) ? g_deg[gid] : 0;
    #pragma unroll
    for (int off = 16; off; off >>= 1) v += __shfl_xor_sync(0xffffffffu, v, off);
    if ((threadIdx.x & 31) == 0) red[threadIdx.x >> 5] = v;
    __syncthreads();
    if (threadIdx.x == 0) {
        int s = 0;
        #pragma unroll
        for (int i = 0; i < SCAN_BLK / 32; i++) s += red[i];
        g_bsum[blockIdx.x] = s;
    }
}

__global__ void __launch_bounds__(SCAN_BLK) k_scanB()   // scan 196 block sums
{
    __shared__ int s[SCAN_BLK];
    const int t = threadIdx.x;
    int v = (t < N_SBLK) ? g_bsum[t] : 0;
    s[t] = v;
    __syncthreads();
    #pragma unroll
    for (int off = 1; off < SCAN_BLK; off <<= 1) {
        int u = (t >= off) ? s[t - off] : 0;
        __syncthreads();
        s[t] += u;
        __syncthreads();
    }
    if (t < N_SBLK) g_boff[t] = s[t] - v;      // exclusive
    if (t == N_SBLK - 1) g_off[N_NODES] = s[t];
}

__global__ void __launch_bounds__(SCAN_BLK) k_scanC()   // per-block exclusive scan + write
{
    __shared__ int s[SCAN_BLK];
    const int t = threadIdx.x;
    const int gid = blockIdx.x * SCAN_BLK + t;
    int v = (gid < N_NODES) ? g_deg[gid] : 0;
    s[t] = v;
    __syncthreads();
    #pragma unroll
    for (int off = 1; off < SCAN_BLK; off <<= 1) {
        int u = (t >= off) ? s[t - off] : 0;
        __syncthreads();
        s[t] += u;
        __syncthreads();
    }
    if (gid < N_NODES) {
        const int o = g_boff[blockIdx.x] + s[t] - v;   // exclusive
        g_off[gid] = o;
        g_cur[gid] = o;
    }
}

// ============================================================================
// K2: logits -> exp -> direct CSR scatter. Half-warp per edge, 4 edges in
// flight per half-warp (MLP=4). Lanes 0-3 parallelize the scalar tail.
// ============================================================================
__global__ void __launch_bounds__(256) k2_scatter(
    const float* __restrict__ rh,
    const float* __restrict__ attn,
    const int* __restrict__ src,
    const int* __restrict__ dst)
{
    const int tid = blockIdx.x * blockDim.x + threadIdx.x;
    const int hw_id = tid >> 4;
    const int l = tid & 15;
    const int nhw = (gridDim.x * blockDim.x) >> 4;

    const float4 w3 = ((const float4*)(attn + 2 * OUT_DIM))[l];

    for (int e0 = hw_id * 4; e0 < E_EDGES; e0 += nhw * 4) {
        const float4 r0 = ((const float4*)(rh + (size_t)(e0 + 0) * OUT_DIM))[l];
        const float4 r1 = ((const float4*)(rh + (size_t)(e0 + 1) * OUT_DIM))[l];
        const float4 r2 = ((const float4*)(rh + (size_t)(e0 + 2) * OUT_DIM))[l];
        const float4 r3 = ((const float4*)(rh + (size_t)(e0 + 3) * OUT_DIM))[l];

        float p0 = r0.x * w3.x + r0.y * w3.y + r0.z * w3.z + r0.w * w3.w;
        float p1 = r1.x * w3.x + r1.y * w3.y + r1.z * w3.z + r1.w * w3.w;
        float p2 = r2.x * w3.x + r2.y * w3.y + r2.z * w3.z + r2.w * w3.w;
        float p3 = r3.x * w3.x + r3.y * w3.y + r3.z * w3.z + r3.w * w3.w;
        #pragma unroll
        for (int off = 8; off; off >>= 1) {
            p0 += __shfl_xor_sync(0xffffffffu, p0, off, 16);
            p1 += __shfl_xor_sync(0xffffffffu, p1, off, 16);
            p2 += __shfl_xor_sync(0xffffffffu, p2, off, 16);
            p3 += __shfl_xor_sync(0xffffffffu, p3, off, 16);
        }
        if (l < 4) {
            const int e = e0 + l;
            const float p = (l == 0) ? p0 : (l == 1) ? p1 : (l == 2) ? p2 : p3;
            const int s = src[e];
            const int d = dst[e];
            const float a = g_s1[s] + g_s2[d] + p;
            const float ev = (a > 0.f) ? a : 0.01f * a;   // leaky relu
            const float ex = __expf(ev);                  // no max-sub: |ev| small
            const int pos = atomicAdd(&g_cur[d], 1);
            g_cedge[pos] = make_int2(s, __float_as_int(ex));
        }
    }
}

// ============================================================================
// K_agg: full warp per node; half-warp per edge, software-pipelined so the
// cedge load for iteration i+1 is in flight while z-gathers of iteration i
// resolve. Payload holds exp(e). Fused self-loop GEMV + normalize + relu.
// ============================================================================
__global__ void __launch_bounds__(256) k_agg(
    const float* __restrict__ LW,   // [64][64] row-major = [k][j]
    float* __restrict__ out)
{
    __shared__ __align__(16) float Ls[OUT_DIM * OUT_DIM];
    for (int i = threadIdx.x; i < OUT_DIM * OUT_DIM / 4; i += blockDim.x)
        ((float4*)Ls)[i] = ((const float4*)LW)[i];
    __syncthreads();

    const int node = (blockIdx.x * blockDim.x + threadIdx.x) >> 5;
    const int l = threadIdx.x & 31;
    const int half = l >> 4;        // 0 or 1
    const int lh = l & 15;          // lane within half
    if (node >= N_NODES) return;

    const int beg = g_off[node];
    const int end = g_off[node + 1];

    if (beg == end) {
        if (half == 0)
            *(float4*)&out[(size_t)node * OUT_DIM + 4 * lh] = make_float4(0.f, 0.f, 0.f, 0.f);
        return;
    }

    // ---- pipelined gather-accumulate: half handles i = beg+half, +2, +4 ...
    float4 acc = make_float4(0.f, 0.f, 0.f, 0.f);
    float denom = 0.f;

    int i = beg + half;
    bool vA = i < end;
    bool vB = i + 2 < end;
    int2 eA = vA ? g_cedge[i] : make_int2(0, 0);
    int2 eB = vB ? g_cedge[i + 2] : make_int2(0, 0);

    while (vA) {
        // prefetch next pair while this pair's z rows load
        const bool nvA = i + 4 < end;
        const bool nvB = i + 6 < end;
        const int2 nA = nvA ? g_cedge[i + 4] : make_int2(0, 0);
        const int2 nB = nvB ? g_cedge[i + 6] : make_int2(0, 0);

        const float x0 = __int_as_float(eA.y);
        const float4 z0 = *(const float4*)&g_z[(size_t)eA.x * OUT_DIM + 4 * lh];
        if (vB) {
            const float x1 = __int_as_float(eB.y);
            const float4 z1 = *(const float4*)&g_z[(size_t)eB.x * OUT_DIM + 4 * lh];
            denom += x0 + x1;
            acc.x += x0 * z0.x + x1 * z1.x;
            acc.y += x0 * z0.y + x1 * z1.y;
            acc.z += x0 * z0.z + x1 * z1.z;
            acc.w += x0 * z0.w + x1 * z1.w;
        } else {
            denom += x0;
            acc.x += x0 * z0.x;
            acc.y += x0 * z0.y;
            acc.z += x0 * z0.z;
            acc.w += x0 * z0.w;
        }
        eA = nA; eB = nB; vA = nvA; vB = nvB; i += 4;
    }

    // ---- self-loop GEMV: half h covers k in [32h, 32h+32) ----
    const float2 zn = *(const float2*)&g_z[(size_t)node * OUT_DIM + 2 * l];
    float4 sl = make_float4(0.f, 0.f, 0.f, 0.f);
    #pragma unroll
    for (int kk = 0; kk < 32; kk++) {
        const int k = half * 32 + kk;
        const float zk = __shfl_sync(0xffffffffu, (k & 1) ? zn.y : zn.x, k >> 1);
        const float4 lw = *(const float4*)&Ls[k * OUT_DIM + 4 * lh];
        sl.x += zk * lw.x;
        sl.y += zk * lw.y;
        sl.z += zk * lw.z;
        sl.w += zk * lw.w;
    }

    // ---- combine halves (lane <-> lane+16) ----
    acc.x += __shfl_xor_sync(0xffffffffu, acc.x, 16);
    acc.y += __shfl_xor_sync(0xffffffffu, acc.y, 16);
    acc.z += __shfl_xor_sync(0xffffffffu, acc.z, 16);
    acc.w += __shfl_xor_sync(0xffffffffu, acc.w, 16);
    sl.x  += __shfl_xor_sync(0xffffffffu, sl.x, 16);
    sl.y  += __shfl_xor_sync(0xffffffffu, sl.y, 16);
    sl.z  += __shfl_xor_sync(0xffffffffu, sl.z, 16);
    sl.w  += __shfl_xor_sync(0xffffffffu, sl.w, 16);
    denom += __shfl_xor_sync(0xffffffffu, denom, 16);

    if (half == 0) {
        const float inv = 1.0f / denom;
        float4 o;
        o.x = fmaxf(acc.x * inv + sl.x, 0.f);
        o.y = fmaxf(acc.y * inv + sl.y, 0.f);
        o.z = fmaxf(acc.z * inv + sl.z, 0.f);
        o.w = fmaxf(acc.w * inv + sl.w, 0.f);
        *(float4*)&out[(size_t)node * OUT_DIM + 4 * lh] = o;
    }
}

// ============================================================================
// launch
// ============================================================================
extern "C" void kernel_launch(void* const* d_in, const int* in_sizes, int n_in,
                              void* d_out, int out_size)
{
    const float* h    = (const float*)d_in[0];
    const float* rh   = (const float*)d_in[1];
    const float* W    = (const float*)d_in[2];
    const float* attn = (const float*)d_in[3];
    const float* LW   = (const float*)d_in[4];
    const int*   src  = (const int*)d_in[5];
    const int*   dst  = (const int*)d_in[6];
    float* out = (float*)d_out;

    k1_node<<<1024, 128>>>(h, W, attn);
    k_count<<<(E_EDGES + 255) / 256, 256>>>(dst);
    k_scanA<<<N_SBLK, SCAN_BLK>>>();
    k_scanB<<<1, SCAN_BLK>>>();
    k_scanC<<<N_SBLK, SCAN_BLK>>>();
    k2_scatter<<<1184, 256>>>(rh, attn, src, dst);
    k_agg<<<(N_NODES * 32 + 255) / 256, 256>>>(LW, out);
}

// round 6
// speedup vs baseline: 1.8065x; 1.0532x over previous
#include <cuda_runtime.h>

#define N_NODES 50000
#define E_EDGES 800000
#define IN_DIM  128
#define OUT_DIM 64

#define SCAN_BLK 256
#define N_SBLK ((N_NODES + SCAN_BLK - 1) / SCAN_BLK)   // 196
#define K1_BLOCKS 1024
#define CNT_BLOCKS 1024

// ---------------- scratch (device globals; allocation-free) ----------------
__device__ __align__(16) float g_z[N_NODES * OUT_DIM];   // 12.8 MB (L2-resident)
__device__ float g_s1[N_NODES];
__device__ float g_s2[N_NODES];
__device__ int   g_deg[N_NODES];        // zero at call entry (BSS / re-zeroed by scanC)
__device__ int   g_off[N_NODES + 1];    // CSR offsets by dst
__device__ int   g_cur[N_NODES];        // running fill cursor
__device__ int   g_bsum[N_SBLK];        // per-block degree sums
__device__ __align__(8) int2 g_cedge[E_EDGES];  // packed {src, exp_bits} per CSR slot

// ============================================================================
// K_fused: blocks [0, K1_BLOCKS) run the z-GEMM (+s1/s2); the rest histogram
// dst degrees (independent data; overlaps latency-bound atomics under FMAs).
// ============================================================================
__global__ void __launch_bounds__(128) k_fused(
    const float* __restrict__ h,
    const float* __restrict__ W,     // [64][128] row-major
    const float* __restrict__ attn,  // [192] = w1 | w2 | w3
    const int*   __restrict__ dst)
{
    __shared__ __align__(16) float Wts[IN_DIM * 66];      // transposed, padded
    __shared__ __align__(16) float hw[4][IN_DIM][4];      // [warp][k][node-slot]

    const int tid = threadIdx.x;

    if (blockIdx.x >= K1_BLOCKS) {
        // ---------------- degree count (g_deg starts zeroed) ----------------
        const int cbid = blockIdx.x - K1_BLOCKS;
        const int t4 = cbid * 128 + tid;                 // int4 index
        const int n4 = E_EDGES / 4;
        const int stride = CNT_BLOCKS * 128;
        for (int i = t4; i < n4; i += stride) {
            const int4 d = ((const int4*)dst)[i];
            atomicAdd(&g_deg[d.x], 1);
            atomicAdd(&g_deg[d.y], 1);
            atomicAdd(&g_deg[d.z], 1);
            atomicAdd(&g_deg[d.w], 1);
        }
        return;
    }

    // -------------------------- z GEMM ------------------------------------
    for (int i = tid; i < OUT_DIM * IN_DIM; i += blockDim.x) {
        int j = i >> 7;
        int k = i & 127;
        Wts[k * 66 + j] = W[i];
    }
    __syncthreads();

    const int w = tid >> 5;
    const int l = tid & 31;

    const float2 w1 = ((const float2*)attn)[l];
    const float2 w2 = ((const float2*)(attn + OUT_DIM))[l];

    const int ntasks_stride = K1_BLOCKS * 4;
    for (int task = blockIdx.x * 4 + w; task < N_NODES / 4; task += ntasks_stride) {
        const int node0 = task * 4;

        #pragma unroll
        for (int m = 0; m < 4; m++) {
            const float* hp = h + (size_t)(node0 + m) * IN_DIM;
            #pragma unroll
            for (int t = 0; t < 4; t++)
                hw[w][t * 32 + l][m] = hp[t * 32 + l];
        }
        __syncwarp();

        float a0x = 0.f, a0y = 0.f, a0z = 0.f, a0w = 0.f;
        float a1x = 0.f, a1y = 0.f, a1z = 0.f, a1w = 0.f;
        #pragma unroll 16
        for (int k = 0; k < IN_DIM; k++) {
            const float4 hq = *(const float4*)&hw[w][k][0];
            const float2 wv = *(const float2*)&Wts[k * 66 + 2 * l];
            a0x += wv.x * hq.x; a0y += wv.x * hq.y; a0z += wv.x * hq.z; a0w += wv.x * hq.w;
            a1x += wv.y * hq.x; a1y += wv.y * hq.y; a1z += wv.y * hq.z; a1w += wv.y * hq.w;
        }
        __syncwarp();

        const float acc0[4] = {a0x, a0y, a0z, a0w};
        const float acc1[4] = {a1x, a1y, a1z, a1w};
        #pragma unroll
        for (int m = 0; m < 4; m++) {
            const int node = node0 + m;
            const float zx = acc0[m], zy = acc1[m];
            *(float2*)&g_z[(size_t)node * OUT_DIM + 2 * l] = make_float2(zx, zy);
            float v1 = zx * w1.x + zy * w1.y;
            float v2 = zx * w2.x + zy * w2.y;
            #pragma unroll
            for (int off = 16; off; off >>= 1) {
                v1 += __shfl_xor_sync(0xffffffffu, v1, off);
                v2 += __shfl_xor_sync(0xffffffffu, v2, off);
            }
            if (l == 0) {
                g_s1[node] = v1;
                g_s2[node] = v2;
            }
        }
    }
}

// ============================================================================
// scanA: per-block degree sums
// ============================================================================
__global__ void __launch_bounds__(SCAN_BLK) k_scanA()
{
    __shared__ int red[SCAN_BLK / 32];
    const int gid = blockIdx.x * SCAN_BLK + threadIdx.x;
    int v = (gid < N_NODES) ? g_deg[gid] : 0;
    #pragma unroll
    for (int off = 16; off; off >>= 1) v += __shfl_xor_sync(0xffffffffu, v, off);
    if ((threadIdx.x & 31) == 0) red[threadIdx.x >> 5] = v;
    __syncthreads();
    if (threadIdx.x == 0) {
        int s = 0;
        #pragma unroll
        for (int i = 0; i < SCAN_BLK / 32; i++) s += red[i];
        g_bsum[blockIdx.x] = s;
    }
}

// ============================================================================
// scanC: block-prefix (direct reduce of g_bsum) + local exclusive scan +
// write off/cur + re-zero deg for the next call.
// ============================================================================
__global__ void __launch_bounds__(SCAN_BLK) k_scanC()
{
    __shared__ int s[SCAN_BLK];
    __shared__ int red[SCAN_BLK / 32];
    __shared__ int s_pre;

    const int t = threadIdx.x;
    const int bid = blockIdx.x;
    const int gid = bid * SCAN_BLK + t;

    // prefix = sum of g_bsum[0..bid)
    int mine = (t < bid) ? g_bsum[t] : 0;     // N_SBLK <= SCAN_BLK
    #pragma unroll
    for (int off = 16; off; off >>= 1) mine += __shfl_xor_sync(0xffffffffu, mine, off);
    if ((t & 31) == 0) red[t >> 5] = mine;
    __syncthreads();
    if (t == 0) {
        int p = 0;
        #pragma unroll
        for (int i = 0; i < SCAN_BLK / 32; i++) p += red[i];
        s_pre = p;
    }

    int v = (gid < N_NODES) ? g_deg[gid] : 0;
    s[t] = v;
    __syncthreads();
    #pragma unroll
    for (int off = 1; off < SCAN_BLK; off <<= 1) {
        int u = (t >= off) ? s[t - off] : 0;
        __syncthreads();
        s[t] += u;
        __syncthreads();
    }

    const int pre = s_pre;
    if (gid < N_NODES) {
        const int o = pre + s[t] - v;   // exclusive
        g_off[gid] = o;
        g_cur[gid] = o;
        g_deg[gid] = 0;                 // ready for next call
        if (gid == N_NODES - 1) g_off[N_NODES] = pre + s[t];
    }
}

// ============================================================================
// K2: logits -> exp -> direct CSR scatter. Half-warp per edge, 8 edges in
// flight per half-warp (MLP=8). Lanes 0-7 parallelize the scalar tail.
// E_EDGES % 8 == 0.
// ============================================================================
__global__ void __launch_bounds__(256) k2_scatter(
    const float* __restrict__ rh,
    const float* __restrict__ attn,
    const int* __restrict__ src,
    const int* __restrict__ dst)
{
    const int tid = blockIdx.x * blockDim.x + threadIdx.x;
    const int hw_id = tid >> 4;
    const int l = tid & 15;
    const int nhw = (gridDim.x * blockDim.x) >> 4;

    const float4 w3 = ((const float4*)(attn + 2 * OUT_DIM))[l];

    for (int e0 = hw_id * 8; e0 < E_EDGES; e0 += nhw * 8) {
        float p[8];
        #pragma unroll
        for (int j = 0; j < 8; j++) {
            const float4 r = ((const float4*)(rh + (size_t)(e0 + j) * OUT_DIM))[l];
            p[j] = r.x * w3.x + r.y * w3.y + r.z * w3.z + r.w * w3.w;
        }
        #pragma unroll
        for (int off = 8; off; off >>= 1) {
            #pragma unroll
            for (int j = 0; j < 8; j++)
                p[j] += __shfl_xor_sync(0xffffffffu, p[j], off, 16);
        }
        if (l < 8) {
            const int e = e0 + l;
            const float pv = (l == 0) ? p[0] : (l == 1) ? p[1] : (l == 2) ? p[2] :
                             (l == 3) ? p[3] : (l == 4) ? p[4] : (l == 5) ? p[5] :
                             (l == 6) ? p[6] : p[7];
            const int s = src[e];
            const int d = dst[e];
            const float a = g_s1[s] + g_s2[d] + pv;
            const float ev = (a > 0.f) ? a : 0.01f * a;   // leaky relu
            const float ex = __expf(ev);                  // no max-sub: |ev| small
            const int pos = atomicAdd(&g_cur[d], 1);
            g_cedge[pos] = make_int2(s, __float_as_int(ex));
        }
    }
}

// ============================================================================
// K_agg: full warp per node; each half-warp consumes groups of 4 edges
// (branch-free: dummy slots load z-row 0 with weight 0), next group
// prefetched -> up to 8 edge-loads in flight per warp.
// Fused self-loop GEMV + normalize + relu.
// ============================================================================
__global__ void __launch_bounds__(256) k_agg(
    const float* __restrict__ LW,   // [64][64] row-major = [k][j]
    float* __restrict__ out)
{
    __shared__ __align__(16) float Ls[OUT_DIM * OUT_DIM];
    for (int i = threadIdx.x; i < OUT_DIM * OUT_DIM / 4; i += blockDim.x)
        ((float4*)Ls)[i] = ((const float4*)LW)[i];
    __syncthreads();

    const int node = (blockIdx.x * blockDim.x + threadIdx.x) >> 5;
    const int l = threadIdx.x & 31;
    const int half = l >> 4;        // 0 or 1
    const int lh = l & 15;          // lane within half
    if (node >= N_NODES) return;

    const int beg = g_off[node];
    const int end = g_off[node + 1];

    if (beg == end) {
        if (half == 0)
            *(float4*)&out[(size_t)node * OUT_DIM + 4 * lh] = make_float4(0.f, 0.f, 0.f, 0.f);
        return;
    }

    // ---- gather-accumulate: half h owns groups [beg+8k+4h, +4) ----
    float4 acc = make_float4(0.f, 0.f, 0.f, 0.f);
    float denom = 0.f;

    int base = beg + 4 * half;
    int2 c0 = make_int2(0, 0), c1 = make_int2(0, 0);
    int2 c2 = make_int2(0, 0), c3 = make_int2(0, 0);
    if (base + 0 < end) c0 = g_cedge[base + 0];
    if (base + 1 < end) c1 = g_cedge[base + 1];
    if (base + 2 < end) c2 = g_cedge[base + 2];
    if (base + 3 < end) c3 = g_cedge[base + 3];

    while (base < end) {
        const int nb = base + 8;
        int2 n0 = make_int2(0, 0), n1 = make_int2(0, 0);
        int2 n2 = make_int2(0, 0), n3 = make_int2(0, 0);
        if (nb + 0 < end) n0 = g_cedge[nb + 0];
        if (nb + 1 < end) n1 = g_cedge[nb + 1];
        if (nb + 2 < end) n2 = g_cedge[nb + 2];
        if (nb + 3 < end) n3 = g_cedge[nb + 3];

        const float x0 = __int_as_float(c0.y);
        const float x1 = __int_as_float(c1.y);
        const float x2 = __int_as_float(c2.y);
        const float x3 = __int_as_float(c3.y);
        const float4 z0 = *(const float4*)&g_z[(size_t)c0.x * OUT_DIM + 4 * lh];
        const float4 z1 = *(const float4*)&g_z[(size_t)c1.x * OUT_DIM + 4 * lh];
        const float4 z2 = *(const float4*)&g_z[(size_t)c2.x * OUT_DIM + 4 * lh];
        const float4 z3 = *(const float4*)&g_z[(size_t)c3.x * OUT_DIM + 4 * lh];

        denom += (x0 + x1) + (x2 + x3);
        acc.x += x0 * z0.x + x1 * z1.x + x2 * z2.x + x3 * z3.x;
        acc.y += x0 * z0.y + x1 * z1.y + x2 * z2.y + x3 * z3.y;
        acc.z += x0 * z0.z + x1 * z1.z + x2 * z2.z + x3 * z3.z;
        acc.w += x0 * z0.w + x1 * z1.w + x2 * z2.w + x3 * z3.w;

        c0 = n0; c1 = n1; c2 = n2; c3 = n3;
        base = nb;
    }

    // ---- self-loop GEMV: half h covers k in [32h, 32h+32) ----
    const float2 zn = *(const float2*)&g_z[(size_t)node * OUT_DIM + 2 * l];
    float4 sl = make_float4(0.f, 0.f, 0.f, 0.f);
    #pragma unroll
    for (int kk = 0; kk < 32; kk++) {
        const int k = half * 32 + kk;
        const float zk = __shfl_sync(0xffffffffu, (k & 1) ? zn.y : zn.x, k >> 1);
        const float4 lw = *(const float4*)&Ls[k * OUT_DIM + 4 * lh];
        sl.x += zk * lw.x;
        sl.y += zk * lw.y;
        sl.z += zk * lw.z;
        sl.w += zk * lw.w;
    }

    // ---- combine halves (lane <-> lane+16) ----
    acc.x += __shfl_xor_sync(0xffffffffu, acc.x, 16);
    acc.y += __shfl_xor_sync(0xffffffffu, acc.y, 16);
    acc.z += __shfl_xor_sync(0xffffffffu, acc.z, 16);
    acc.w += __shfl_xor_sync(0xffffffffu, acc.w, 16);
    sl.x  += __shfl_xor_sync(0xffffffffu, sl.x, 16);
    sl.y  += __shfl_xor_sync(0xffffffffu, sl.y, 16);
    sl.z  += __shfl_xor_sync(0xffffffffu, sl.z, 16);
    sl.w  += __shfl_xor_sync(0xffffffffu, sl.w, 16);
    denom += __shfl_xor_sync(0xffffffffu, denom, 16);

    if (half == 0) {
        const float inv = 1.0f / denom;
        float4 o;
        o.x = fmaxf(acc.x * inv + sl.x, 0.f);
        o.y = fmaxf(acc.y * inv + sl.y, 0.f);
        o.z = fmaxf(acc.z * inv + sl.z, 0.f);
        o.w = fmaxf(acc.w * inv + sl.w, 0.f);
        *(float4*)&out[(size_t)node * OUT_DIM + 4 * lh] = o;
    }
}

// ============================================================================
// launch
// ============================================================================
extern "C" void kernel_launch(void* const* d_in, const int* in_sizes, int n_in,
                              void* d_out, int out_size)
{
    const float* h    = (const float*)d_in[0];
    const float* rh   = (const float*)d_in[1];
    const float* W    = (const float*)d_in[2];
    const float* attn = (const float*)d_in[3];
    const float* LW   = (const float*)d_in[4];
    const int*   src  = (const int*)d_in[5];
    const int*   dst  = (const int*)d_in[6];
    float* out = (float*)d_out;

    k_fused<<<K1_BLOCKS + CNT_BLOCKS, 128>>>(h, W, attn, dst);
    k_scanA<<<N_SBLK, SCAN_BLK>>>();
    k_scanC<<<N_SBLK, SCAN_BLK>>>();
    k2_scatter<<<1184, 256>>>(rh, attn, src, dst);
    k_agg<<<(N_NODES * 32 + 255) / 256, 256>>>(LW, out);
}

// round 7
// speedup vs baseline: 1.9155x; 1.0603x over previous
#include <cuda_runtime.h>

#define N_NODES 50000
#define E_EDGES 800000
#define IN_DIM  128
#define OUT_DIM 64

#define SCAN_BLK 256
#define N_SBLK ((N_NODES + SCAN_BLK - 1) / SCAN_BLK)   // 196
#define K1_BLOCKS 1024
#define CNT_BLOCKS 1024

// ---------------- scratch (device globals; allocation-free) ----------------
__device__ __align__(16) float g_z[N_NODES * OUT_DIM];   // 12.8 MB (L2-resident)
__device__ float g_s1[N_NODES];
__device__ float g_s2[N_NODES];
__device__ int   g_deg[N_NODES];        // zero at call entry (BSS / re-zeroed by scanC)
__device__ int   g_off[N_NODES + 1];    // CSR offsets by dst
__device__ int   g_cur[N_NODES];        // running fill cursor
__device__ int   g_bsum[N_SBLK];        // per-block degree sums
__device__ __align__(8) int2 g_cedge[E_EDGES];  // packed {src, exp_bits} per CSR slot

// ============================================================================
// K_fused: blocks [0, K1_BLOCKS) run the z-GEMM (+s1/s2); the rest histogram
// dst degrees (independent work overlapped).
// ============================================================================
__global__ void __launch_bounds__(128) k_fused(
    const float* __restrict__ h,
    const float* __restrict__ W,     // [64][128] row-major
    const float* __restrict__ attn,  // [192] = w1 | w2 | w3
    const int*   __restrict__ dst)
{
    __shared__ __align__(16) float Wts[IN_DIM * 66];      // transposed, padded
    __shared__ __align__(16) float hw[4][IN_DIM][4];      // [warp][k][node-slot]

    const int tid = threadIdx.x;

    if (blockIdx.x >= K1_BLOCKS) {
        const int cbid = blockIdx.x - K1_BLOCKS;
        const int t4 = cbid * 128 + tid;                 // int4 index
        const int n4 = E_EDGES / 4;
        const int stride = CNT_BLOCKS * 128;
        for (int i = t4; i < n4; i += stride) {
            const int4 d = ((const int4*)dst)[i];
            atomicAdd(&g_deg[d.x], 1);
            atomicAdd(&g_deg[d.y], 1);
            atomicAdd(&g_deg[d.z], 1);
            atomicAdd(&g_deg[d.w], 1);
        }
        return;
    }

    for (int i = tid; i < OUT_DIM * IN_DIM; i += blockDim.x) {
        int j = i >> 7;
        int k = i & 127;
        Wts[k * 66 + j] = W[i];
    }
    __syncthreads();

    const int w = tid >> 5;
    const int l = tid & 31;

    const float2 w1 = ((const float2*)attn)[l];
    const float2 w2 = ((const float2*)(attn + OUT_DIM))[l];

    const int ntasks_stride = K1_BLOCKS * 4;
    for (int task = blockIdx.x * 4 + w; task < N_NODES / 4; task += ntasks_stride) {
        const int node0 = task * 4;

        #pragma unroll
        for (int m = 0; m < 4; m++) {
            const float* hp = h + (size_t)(node0 + m) * IN_DIM;
            #pragma unroll
            for (int t = 0; t < 4; t++)
                hw[w][t * 32 + l][m] = hp[t * 32 + l];
        }
        __syncwarp();

        float a0x = 0.f, a0y = 0.f, a0z = 0.f, a0w = 0.f;
        float a1x = 0.f, a1y = 0.f, a1z = 0.f, a1w = 0.f;
        #pragma unroll 16
        for (int k = 0; k < IN_DIM; k++) {
            const float4 hq = *(const float4*)&hw[w][k][0];
            const float2 wv = *(const float2*)&Wts[k * 66 + 2 * l];
            a0x += wv.x * hq.x; a0y += wv.x * hq.y; a0z += wv.x * hq.z; a0w += wv.x * hq.w;
            a1x += wv.y * hq.x; a1y += wv.y * hq.y; a1z += wv.y * hq.z; a1w += wv.y * hq.w;
        }
        __syncwarp();

        const float acc0[4] = {a0x, a0y, a0z, a0w};
        const float acc1[4] = {a1x, a1y, a1z, a1w};
        #pragma unroll
        for (int m = 0; m < 4; m++) {
            const int node = node0 + m;
            const float zx = acc0[m], zy = acc1[m];
            *(float2*)&g_z[(size_t)node * OUT_DIM + 2 * l] = make_float2(zx, zy);
            float v1 = zx * w1.x + zy * w1.y;
            float v2 = zx * w2.x + zy * w2.y;
            #pragma unroll
            for (int off = 16; off; off >>= 1) {
                v1 += __shfl_xor_sync(0xffffffffu, v1, off);
                v2 += __shfl_xor_sync(0xffffffffu, v2, off);
            }
            if (l == 0) {
                g_s1[node] = v1;
                g_s2[node] = v2;
            }
        }
    }
}

// ============================================================================
// scanA: per-block degree sums
// ============================================================================
__global__ void __launch_bounds__(SCAN_BLK) k_scanA()
{
    __shared__ int red[SCAN_BLK / 32];
    const int gid = blockIdx.x * SCAN_BLK + threadIdx.x;
    int v = (gid < N_NODES) ? g_deg[gid] : 0;
    #pragma unroll
    for (int off = 16; off; off >>= 1) v += __shfl_xor_sync(0xffffffffu, v, off);
    if ((threadIdx.x & 31) == 0) red[threadIdx.x >> 5] = v;
    __syncthreads();
    if (threadIdx.x == 0) {
        int s = 0;
        #pragma unroll
        for (int i = 0; i < SCAN_BLK / 32; i++) s += red[i];
        g_bsum[blockIdx.x] = s;
    }
}

// ============================================================================
// scanC: block-prefix + local exclusive scan + write off/cur + re-zero deg
// ============================================================================
__global__ void __launch_bounds__(SCAN_BLK) k_scanC()
{
    __shared__ int s[SCAN_BLK];
    __shared__ int red[SCAN_BLK / 32];
    __shared__ int s_pre;

    const int t = threadIdx.x;
    const int bid = blockIdx.x;
    const int gid = bid * SCAN_BLK + t;

    int mine = (t < bid) ? g_bsum[t] : 0;     // N_SBLK <= SCAN_BLK
    #pragma unroll
    for (int off = 16; off; off >>= 1) mine += __shfl_xor_sync(0xffffffffu, mine, off);
    if ((t & 31) == 0) red[t >> 5] = mine;
    __syncthreads();
    if (t == 0) {
        int p = 0;
        #pragma unroll
        for (int i = 0; i < SCAN_BLK / 32; i++) p += red[i];
        s_pre = p;
    }

    int v = (gid < N_NODES) ? g_deg[gid] : 0;
    s[t] = v;
    __syncthreads();
    #pragma unroll
    for (int off = 1; off < SCAN_BLK; off <<= 1) {
        int u = (t >= off) ? s[t - off] : 0;
        __syncthreads();
        s[t] += u;
        __syncthreads();
    }

    const int pre = s_pre;
    if (gid < N_NODES) {
        const int o = pre + s[t] - v;   // exclusive
        g_off[gid] = o;
        g_cur[gid] = o;
        g_deg[gid] = 0;                 // ready for next call
        if (gid == N_NODES - 1) g_off[N_NODES] = pre + s[t];
    }
}

// ============================================================================
// K2: logits -> exp -> direct CSR scatter. Half-warp per edge, 4 edges in
// flight (measured-best MLP). Streaming loads keep g_z resident in L2.
// ============================================================================
__global__ void __launch_bounds__(256) k2_scatter(
    const float* __restrict__ rh,
    const float* __restrict__ attn,
    const int* __restrict__ src,
    const int* __restrict__ dst)
{
    const int tid = blockIdx.x * blockDim.x + threadIdx.x;
    const int hw_id = tid >> 4;
    const int l = tid & 15;
    const int nhw = (gridDim.x * blockDim.x) >> 4;

    const float4 w3 = ((const float4*)(attn + 2 * OUT_DIM))[l];

    for (int e0 = hw_id * 4; e0 < E_EDGES; e0 += nhw * 4) {
        const float4 r0 = __ldcs((const float4*)(rh + (size_t)(e0 + 0) * OUT_DIM) + l);
        const float4 r1 = __ldcs((const float4*)(rh + (size_t)(e0 + 1) * OUT_DIM) + l);
        const float4 r2 = __ldcs((const float4*)(rh + (size_t)(e0 + 2) * OUT_DIM) + l);
        const float4 r3 = __ldcs((const float4*)(rh + (size_t)(e0 + 3) * OUT_DIM) + l);

        float p0 = r0.x * w3.x + r0.y * w3.y + r0.z * w3.z + r0.w * w3.w;
        float p1 = r1.x * w3.x + r1.y * w3.y + r1.z * w3.z + r1.w * w3.w;
        float p2 = r2.x * w3.x + r2.y * w3.y + r2.z * w3.z + r2.w * w3.w;
        float p3 = r3.x * w3.x + r3.y * w3.y + r3.z * w3.z + r3.w * w3.w;
        #pragma unroll
        for (int off = 8; off; off >>= 1) {
            p0 += __shfl_xor_sync(0xffffffffu, p0, off, 16);
            p1 += __shfl_xor_sync(0xffffffffu, p1, off, 16);
            p2 += __shfl_xor_sync(0xffffffffu, p2, off, 16);
            p3 += __shfl_xor_sync(0xffffffffu, p3, off, 16);
        }
        if (l < 4) {
            const int e = e0 + l;
            const float p = (l == 0) ? p0 : (l == 1) ? p1 : (l == 2) ? p2 : p3;
            const int s = src[e];
            const int d = dst[e];
            const float a = g_s1[s] + g_s2[d] + p;
            const float ev = (a > 0.f) ? a : 0.01f * a;   // leaky relu
            const float ex = __expf(ev);                  // no max-sub: |ev| small
            const int pos = atomicAdd(&g_cur[d], 1);
            g_cedge[pos] = make_int2(s, __float_as_int(ex));
        }
    }
}

// ============================================================================
// K_agg: one warp per node. Lanes coalesce-load up to 32 cedge entries in a
// single LDG, then shfl-broadcast each edge's (src, weight). Lane owns output
// dims {2l, 2l+1}. denom is a uniform register (no reduce). Fused self-loop
// GEMV + normalize + relu.
// ============================================================================
__global__ void __launch_bounds__(256) k_agg(
    const float* __restrict__ LW,   // [64][64] row-major = [k][j]
    float* __restrict__ out)
{
    __shared__ __align__(16) float Ls[OUT_DIM * OUT_DIM];
    for (int i = threadIdx.x; i < OUT_DIM * OUT_DIM / 4; i += blockDim.x)
        ((float4*)Ls)[i] = ((const float4*)LW)[i];
    __syncthreads();

    const int node = (blockIdx.x * blockDim.x + threadIdx.x) >> 5;
    const int l = threadIdx.x & 31;
    if (node >= N_NODES) return;

    const int beg = g_off[node];
    const int end = g_off[node + 1];

    if (beg == end) {
        *(float2*)&out[(size_t)node * OUT_DIM + 2 * l] = make_float2(0.f, 0.f);
        return;
    }

    float accx = 0.f, accy = 0.f, denom = 0.f;

    for (int base = beg; base < end; base += 32) {
        const int idx = base + l;
        int2 ce = make_int2(0, 0);                 // weight bits 0 -> exp=0.0f
        if (idx < end) ce = g_cedge[idx];          // ONE coalesced LDG for 32 edges
        const int cnt = min(32, end - base);

        int j = 0;
        for (; j + 4 <= cnt; j += 4) {
            const int   s0 = __shfl_sync(0xffffffffu, ce.x, j);
            const int   s1 = __shfl_sync(0xffffffffu, ce.x, j + 1);
            const int   s2 = __shfl_sync(0xffffffffu, ce.x, j + 2);
            const int   s3 = __shfl_sync(0xffffffffu, ce.x, j + 3);
            const float x0 = __int_as_float(__shfl_sync(0xffffffffu, ce.y, j));
            const float x1 = __int_as_float(__shfl_sync(0xffffffffu, ce.y, j + 1));
            const float x2 = __int_as_float(__shfl_sync(0xffffffffu, ce.y, j + 2));
            const float x3 = __int_as_float(__shfl_sync(0xffffffffu, ce.y, j + 3));
            const float2 z0 = *(const float2*)&g_z[(size_t)s0 * OUT_DIM + 2 * l];
            const float2 z1 = *(const float2*)&g_z[(size_t)s1 * OUT_DIM + 2 * l];
            const float2 z2 = *(const float2*)&g_z[(size_t)s2 * OUT_DIM + 2 * l];
            const float2 z3 = *(const float2*)&g_z[(size_t)s3 * OUT_DIM + 2 * l];
            denom += (x0 + x1) + (x2 + x3);
            accx += x0 * z0.x + x1 * z1.x + x2 * z2.x + x3 * z3.x;
            accy += x0 * z0.y + x1 * z1.y + x2 * z2.y + x3 * z3.y;
        }
        for (; j < cnt; j++) {
            const int   s = __shfl_sync(0xffffffffu, ce.x, j);
            const float x = __int_as_float(__shfl_sync(0xffffffffu, ce.y, j));
            const float2 zz = *(const float2*)&g_z[(size_t)s * OUT_DIM + 2 * l];
            denom += x;
            accx += x * zz.x;
            accy += x * zz.y;
        }
    }

    // ---- self-loop GEMV: full-warp shfl broadcast of z[node] ----
    const float2 zn = *(const float2*)&g_z[(size_t)node * OUT_DIM + 2 * l];
    float slx = 0.f, sly = 0.f;
    #pragma unroll
    for (int k = 0; k < OUT_DIM; k++) {
        const float zk = __shfl_sync(0xffffffffu, (k & 1) ? zn.y : zn.x, k >> 1);
        const float2 lw = *(const float2*)&Ls[k * OUT_DIM + 2 * l];
        slx += zk * lw.x;
        sly += zk * lw.y;
    }

    const float inv = 1.0f / denom;      // denom uniform across lanes
    float2 o;
    o.x = fmaxf(accx * inv + slx, 0.f);
    o.y = fmaxf(accy * inv + sly, 0.f);
    *(float2*)&out[(size_t)node * OUT_DIM + 2 * l] = o;
}

// ============================================================================
// launch
// ============================================================================
extern "C" void kernel_launch(void* const* d_in, const int* in_sizes, int n_in,
                              void* d_out, int out_size)
{
    const float* h    = (const float*)d_in[0];
    const float* rh   = (const float*)d_in[1];
    const float* W    = (const float*)d_in[2];
    const float* attn = (const float*)d_in[3];
    const float* LW   = (const float*)d_in[4];
    const int*   src  = (const int*)d_in[5];
    const int*   dst  = (const int*)d_in[6];
    float* out = (float*)d_out;

    k_fused<<<K1_BLOCKS + CNT_BLOCKS, 128>>>(h, W, attn, dst);
    k_scanA<<<N_SBLK, SCAN_BLK>>>();
    k_scanC<<<N_SBLK, SCAN_BLK>>>();
    k2_scatter<<<1184, 256>>>(rh, attn, src, dst);
    k_agg<<<(N_NODES * 32 + 255) / 256, 256>>>(LW, out);
}